// round 11
// baseline (speedup 1.0000x reference)
#include <cuda_runtime.h>

#define BIGZ 1000000.0f
constexpr int N_ = 8, H_ = 512, W_ = 512, C_ = 32, F_ = 20000, V_ = 10002;
constexpr int HW = H_ * W_;  // 262144

constexpr long long OFF_OUTMAP = 0LL;
constexpr long long OFF_VV     = 67108864LL;
constexpr long long OFF_MASK   = 67118866LL;
constexpr long long OFF_ZB     = 69216018LL;
constexpr long long OFF_P      = 71313170LL;
constexpr long long OFF_D      = 73410322LL;
constexpr long long OFF_BC     = 75507474LL;

// zero at module load; vertex_k restores all-zero after each use.
__device__ int g_face_flag[F_];

__device__ __forceinline__ void stcs2(float* p, float a, float b) {
    float2 v = make_float2(a, b);
    __stcs((float2*)p, v);
}

// ---------------------------------------------------------------------------
// Per-pixel pass, 2 pixels/thread. R10: registers squeezed further —
//  * z[8][2] live range eliminated: zbuf loaded with DEFAULT policy in pass 1
//    (L1-resident, ~32KB/CTA) and re-loaded per layer in pass 2 (L1 hits).
//  * __launch_bounds__(64,12) caps regs at ~80 -> 24 warps/SM (was ~16).
// R9 proved occupancy (not DRAM) is binding: 2px/thread gave 90.3->82.4us.
// ---------------------------------------------------------------------------
__global__ __launch_bounds__(64, 12) void pixel_k(
    const float* __restrict__ zbuf,
    const int*   __restrict__ ptf,
    const float* __restrict__ bary,
    const float* __restrict__ dists,
    const float* __restrict__ fm,
    float*       __restrict__ out)
{
    int g = blockIdx.x * blockDim.x + threadIdx.x;  // 0 .. HW/2-1
    if (g < V_) out[OFF_VV + g] = 0.0f;
    int pix = g << 1;

    // ---- pass 1: coverage count + first-argmin (z NOT kept in regs) -------
    float minv[2];
    int   mini[2];
    int   cnt[2];
#pragma unroll
    for (int j = 0; j < 2; j++) { minv[j] = 3.0e38f; mini[j] = 0; cnt[j] = 0; }

#pragma unroll
    for (int n = 0; n < 8; n++) {
        float2 zz = *(const float2*)(zbuf + n * HW + pix);  // cached (L1)
        float zv[2] = {zz.x, zz.y};
#pragma unroll
        for (int j = 0; j < 2; j++) {
            float v = zv[j];
            cnt[j] += (v > -1.0f) ? 1 : 0;
            float tmp = (v < 0.0f) ? BIGZ : v;
            if (tmp < minv[j]) { minv[j] = tmp; mini[j] = n; }
        }
    }

    // ---- pass 2: per layer, emit masked outputs + colors -------------------
#pragma unroll
    for (int n = 0; n < 8; n++) {
        float2 z2  = *(const float2*)(zbuf + n * HW + pix);  // L1 hit
        int2   pf2 = __ldcs((const int2*)(ptf + n * HW + pix));
        float2 d2  = __ldcs((const float2*)(dists + n * HW + pix));
        const float* bptr = bary + (long long)(n * HW + pix) * 3;
        float2 bA = __ldcs((const float2*)(bptr));
        float2 bB = __ldcs((const float2*)(bptr + 2));
        float2 bC = __ldcs((const float2*)(bptr + 4));
        float bin[6] = {bA.x, bA.y, bB.x, bB.y, bC.x, bC.y};
        float zv[2] = {z2.x, z2.y};
        int   pf[2] = {pf2.x, pf2.y};
        float dd[2] = {d2.x, d2.y};

        float b0[2], b1[2], b2[2];
        int   pr[2];
        bool  valid[2];
        long long base = (long long)n * HW + pix;
        {
            float t0[2], t1[2];
#pragma unroll
            for (int j = 0; j < 2; j++) {
                bool dup = (cnt[j] > 1) && (mini[j] != n);
                int  p   = dup ? -1 : pf[j];
                valid[j] = (p >= 0);
                pr[j]    = valid[j] ? p : 0;
                b0[j]    = dup ? -1.0f : bin[3 * j + 0];
                b1[j]    = dup ? -1.0f : bin[3 * j + 1];
                b2[j]    = dup ? -1.0f : bin[3 * j + 2];
                t0[j]    = dup ? -1.0f : zv[j];      // zb out
                t1[j]    = (float)p;                 // p out
                if (valid[j]) g_face_flag[pr[j]] = 1;
            }
            stcs2(out + OFF_ZB + base, t0[0], t0[1]);
            stcs2(out + OFF_P  + base, t1[0], t1[1]);
#pragma unroll
            for (int j = 0; j < 2; j++) {
                bool dup = (cnt[j] > 1) && (mini[j] != n);
                t0[j] = dup ? -1.0f : dd[j];          // d out
                t1[j] = (zv[j] >= 0.0f) ? 1.0f : 0.0f; // mask out
            }
            stcs2(out + OFF_D    + base, t0[0], t0[1]);
            stcs2(out + OFF_MASK + base, t1[0], t1[1]);
            float* bp = out + OFF_BC + base * 3;
            stcs2(bp,     b0[0], b1[0]);
            stcs2(bp + 2, b2[0], b0[1]);
            stcs2(bp + 4, b1[1], b2[1]);
        }

        // colors: out_map[n][c][h][w]; float2 over w, transposed in regs
        float* om = out + OFF_OUTMAP + (long long)n * C_ * HW + pix;
#pragma unroll
        for (int cq = 0; cq < 8; cq++) {
            int c = cq * 4;
            float col[2][4];
#pragma unroll
            for (int j = 0; j < 2; j++) {
                float4 a = make_float4(0.f, 0.f, 0.f, 0.f);
                if (valid[j]) {
                    const float* fb = fm + pr[j] * 96 + c;  // face_memory[p][i][c]
                    float4 f0 = *(const float4*)(fb);
                    float4 f1 = *(const float4*)(fb + 32);
                    float4 f2 = *(const float4*)(fb + 64);
                    a.x = b0[j] * f0.x + b1[j] * f1.x + b2[j] * f2.x;
                    a.y = b0[j] * f0.y + b1[j] * f1.y + b2[j] * f2.y;
                    a.z = b0[j] * f0.z + b1[j] * f1.z + b2[j] * f2.z;
                    a.w = b0[j] * f0.w + b1[j] * f1.w + b2[j] * f2.w;
                }
                col[j][0] = a.x; col[j][1] = a.y; col[j][2] = a.z; col[j][3] = a.w;
            }
#pragma unroll
            for (int k = 0; k < 4; k++)
                stcs2(om + (long long)(c + k) * HW, col[0][k], col[1][k]);
        }
    }
}

// ---------------------------------------------------------------------------
// Face visibility -> vertex visibility scatter; clears flags for next replay.
// ---------------------------------------------------------------------------
__global__ __launch_bounds__(128) void vertex_k(const int* __restrict__ faces,
                                                float* __restrict__ out) {
    int f = blockIdx.x * blockDim.x + threadIdx.x;
    if (f < F_) {
        int flag = g_face_flag[f];
        int v0 = __ldg(faces + 3 * f + 0);
        int v1 = __ldg(faces + 3 * f + 1);
        int v2 = __ldg(faces + 3 * f + 2);
        if (flag) {
            out[OFF_VV + v0] = 1.0f;
            out[OFF_VV + v1] = 1.0f;
            out[OFF_VV + v2] = 1.0f;
            g_face_flag[f] = 0;
        }
    }
}

extern "C" void kernel_launch(void* const* d_in, const int* in_sizes, int n_in,
                              void* d_out, int out_size) {
    const float* zbuf  = (const float*)d_in[0];
    const int*   ptf   = (const int*)d_in[1];
    const float* bary  = (const float*)d_in[2];
    const float* dists = (const float*)d_in[3];
    const float* fm    = (const float*)d_in[4];
    const int*   faces = (const int*)d_in[5];
    float* out = (float*)d_out;

    pixel_k<<<(HW / 2) / 64, 64>>>(zbuf, ptf, bary, dists, fm, out);
    vertex_k<<<(F_ + 127) / 128, 128>>>(faces, out);
}

// round 13
// speedup vs baseline: 1.2045x; 1.2045x over previous
#include <cuda_runtime.h>

#define BIGZ 1000000.0f
constexpr int N_ = 8, H_ = 512, W_ = 512, C_ = 32, F_ = 20000, V_ = 10002;
constexpr int HW = H_ * W_;  // 262144

constexpr long long OFF_OUTMAP = 0LL;
constexpr long long OFF_VV     = 67108864LL;
constexpr long long OFF_MASK   = 67118866LL;
constexpr long long OFF_ZB     = 69216018LL;
constexpr long long OFF_P      = 71313170LL;
constexpr long long OFF_D      = 73410322LL;
constexpr long long OFF_BC     = 75507474LL;

// zero at module load; vertex_k restores all-zero after each use.
__device__ int g_face_flag[F_];

__device__ __forceinline__ void stcs2(float* p, float a, float b) {
    float2 v = make_float2(a, b);
    __stcs((float2*)p, v);
}

// ---------------------------------------------------------------------------
// Per-pixel pass, 2 pixels/thread. R12: pass-2 layer loop ROLLED
// (#pragma unroll 1) so ptxas only keeps ONE iteration's working set live
// -> organically lower regs -> higher occupancy (R11 showed a forced reg cap
// spills and regresses; R9 showed occupancy is the binding constraint).
// z is re-loaded per layer with default caching: pass 1 pulls it into L1
// (~4KB/CTA; L1 persists within a launch) so these are ~39-cycle hits.
// ---------------------------------------------------------------------------
__global__ __launch_bounds__(64) void pixel_k(
    const float* __restrict__ zbuf,
    const int*   __restrict__ ptf,
    const float* __restrict__ bary,
    const float* __restrict__ dists,
    const float* __restrict__ fm,
    float*       __restrict__ out)
{
    int g = blockIdx.x * blockDim.x + threadIdx.x;  // 0 .. HW/2-1
    if (g < V_) out[OFF_VV + g] = 0.0f;
    int pix = g << 1;

    // ---- pass 1: coverage count + first-argmin (z stays in L1, not regs) --
    float minv[2];
    int   mini[2];
    int   cnt[2];
#pragma unroll
    for (int j = 0; j < 2; j++) { minv[j] = 3.0e38f; mini[j] = 0; cnt[j] = 0; }

#pragma unroll
    for (int n = 0; n < 8; n++) {
        float2 zz = *(const float2*)(zbuf + n * HW + pix);  // default: caches in L1
        float zv[2] = {zz.x, zz.y};
#pragma unroll
        for (int j = 0; j < 2; j++) {
            float v = zv[j];
            cnt[j] += (v > -1.0f) ? 1 : 0;
            float tmp = (v < 0.0f) ? BIGZ : v;
            if (tmp < minv[j]) { minv[j] = tmp; mini[j] = n; }
        }
    }

    // ---- pass 2: rolled over layers; one iteration's state live at a time --
#pragma unroll 1
    for (int n = 0; n < 8; n++) {
        float2 z2  = *(const float2*)(zbuf + n * HW + pix);  // L1 hit
        int2   pf2 = __ldcs((const int2*)(ptf + n * HW + pix));
        float2 d2  = __ldcs((const float2*)(dists + n * HW + pix));
        const float* bptr = bary + (long long)(n * HW + pix) * 3;
        float2 bA = __ldcs((const float2*)(bptr));
        float2 bB = __ldcs((const float2*)(bptr + 2));
        float2 bC = __ldcs((const float2*)(bptr + 4));
        float bin[6] = {bA.x, bA.y, bB.x, bB.y, bC.x, bC.y};
        float zv[2] = {z2.x, z2.y};
        int   pf[2] = {pf2.x, pf2.y};
        float dd[2] = {d2.x, d2.y};

        float zbo[2], po[2], dto[2], mo[2];
        float b0[2], b1[2], b2[2];
        int   pr[2];
        bool  valid[2];
#pragma unroll
        for (int j = 0; j < 2; j++) {
            bool dup = (cnt[j] > 1) && (mini[j] != n);
            int  p   = dup ? -1 : pf[j];
            valid[j] = (p >= 0);
            pr[j]    = valid[j] ? p : 0;
            zbo[j]   = dup ? -1.0f : zv[j];
            po[j]    = (float)p;
            dto[j]   = dup ? -1.0f : dd[j];
            b0[j]    = dup ? -1.0f : bin[3 * j + 0];
            b1[j]    = dup ? -1.0f : bin[3 * j + 1];
            b2[j]    = dup ? -1.0f : bin[3 * j + 2];
            mo[j]    = (zv[j] >= 0.0f) ? 1.0f : 0.0f;
            if (valid[j]) g_face_flag[pr[j]] = 1;  // idempotent flag store
        }

        long long base = (long long)n * HW + pix;
        stcs2(out + OFF_ZB + base,   zbo[0], zbo[1]);
        stcs2(out + OFF_P + base,    po[0],  po[1]);
        stcs2(out + OFF_D + base,    dto[0], dto[1]);
        stcs2(out + OFF_MASK + base, mo[0],  mo[1]);
        float* bp = out + OFF_BC + base * 3;
        stcs2(bp,     b0[0], b1[0]);
        stcs2(bp + 2, b2[0], b0[1]);
        stcs2(bp + 4, b1[1], b2[1]);

        // colors: out_map[n][c][h][w]; float2 over w, transposed in regs
        float* om = out + OFF_OUTMAP + (long long)n * C_ * HW + pix;
#pragma unroll
        for (int cq = 0; cq < 8; cq++) {
            int c = cq * 4;
            float col[2][4];
#pragma unroll
            for (int j = 0; j < 2; j++) {
                float4 a = make_float4(0.f, 0.f, 0.f, 0.f);
                if (valid[j]) {
                    const float* fb = fm + pr[j] * 96 + c;  // face_memory[p][i][c]
                    float4 f0 = *(const float4*)(fb);
                    float4 f1 = *(const float4*)(fb + 32);
                    float4 f2 = *(const float4*)(fb + 64);
                    a.x = b0[j] * f0.x + b1[j] * f1.x + b2[j] * f2.x;
                    a.y = b0[j] * f0.y + b1[j] * f1.y + b2[j] * f2.y;
                    a.z = b0[j] * f0.z + b1[j] * f1.z + b2[j] * f2.z;
                    a.w = b0[j] * f0.w + b1[j] * f1.w + b2[j] * f2.w;
                }
                col[j][0] = a.x; col[j][1] = a.y; col[j][2] = a.z; col[j][3] = a.w;
            }
#pragma unroll
            for (int k = 0; k < 4; k++)
                stcs2(om + (long long)(c + k) * HW, col[0][k], col[1][k]);
        }
    }
}

// ---------------------------------------------------------------------------
// Face visibility -> vertex visibility scatter; clears flags for next replay.
// ---------------------------------------------------------------------------
__global__ __launch_bounds__(128) void vertex_k(const int* __restrict__ faces,
                                                float* __restrict__ out) {
    int f = blockIdx.x * blockDim.x + threadIdx.x;
    if (f < F_) {
        int flag = g_face_flag[f];
        int v0 = __ldg(faces + 3 * f + 0);
        int v1 = __ldg(faces + 3 * f + 1);
        int v2 = __ldg(faces + 3 * f + 2);
        if (flag) {
            out[OFF_VV + v0] = 1.0f;
            out[OFF_VV + v1] = 1.0f;
            out[OFF_VV + v2] = 1.0f;
            g_face_flag[f] = 0;
        }
    }
}

extern "C" void kernel_launch(void* const* d_in, const int* in_sizes, int n_in,
                              void* d_out, int out_size) {
    const float* zbuf  = (const float*)d_in[0];
    const int*   ptf   = (const int*)d_in[1];
    const float* bary  = (const float*)d_in[2];
    const float* dists = (const float*)d_in[3];
    const float* fm    = (const float*)d_in[4];
    const int*   faces = (const int*)d_in[5];
    float* out = (float*)d_out;

    pixel_k<<<(HW / 2) / 64, 64>>>(zbuf, ptf, bary, dists, fm, out);
    vertex_k<<<(F_ + 127) / 128, 128>>>(faces, out);
}